// round 7
// baseline (speedup 1.0000x reference)
#include <cuda_runtime.h>
#include <math.h>

// ---------------- problem constants ----------------
static constexpr int BB   = 8;
static constexpr int TT   = 1024;
static constexpr int CC   = 768;
static constexpr int HH   = 12;
static constexpr int HID  = 1536;
static constexpr int MM   = 16;
static constexpr int PP   = 4;
static constexpr int PREFIX = MM + PP;          // 20
static constexpr int TA   = TT + PREFIX;        // 1044
static constexpr int DH   = CC / HH;            // 64
static constexpr float LR = 0.01f, MUc = 0.9f, DECAY = 0.001f;

// ---------------- scratch (device globals; allocation-free) ----------------
__device__ float g_a  [BB*TT*HID];   // mem-fwd hidden | bwd pre
__device__ float g_b  [BB*TT*HID];   // bwd hh
__device__ float g_c  [BB*TT*HID];   // bwd d_hh/d_pre
__device__ float g_x1 [BB*TT*CC];    // q proj | d_pred
__device__ float g_x2 [BB*TT*CC];    // mem out | keys
__device__ float g_x3 [BB*TT*CC];    // vals
__device__ float g_pool[BB*MM*CC];
__device__ float g_xa [BB*TA*CC];
__device__ float g_hln[BB*TA*CC];
__device__ float g_qkv[BB*TA*3*CC];
__device__ float g_y  [BB*TA*CC];
__device__ float g_fc [BB*TA*4*CC];
__device__ float g_gw0[BB*HID*CC];
__device__ float g_gw1[BB*CC*HID];
__device__ float g_gb0[BB*HID];
__device__ float g_gb1[BB*CC];

// ---------------- generic batched GEMM (128x128 tile, 8x8 microtile) ----------
// C[z] = beta*C[z] + act(alpha * opA(A[z]) @ opB(B[z]) + bias)
// TRA==1 -> use A^T (read A[k*lda+m]); TRB==1 -> x @ W^T (read B[n*ldb+k])
enum { ACT_NONE = 0, ACT_SILU = 1, ACT_GELU = 2 };

template<int TRA, int TRB, int ACT, int BETA>
__global__ void gemm_k(const float* __restrict__ A, const float* __restrict__ Bm,
                       const float* __restrict__ bias, float* __restrict__ Cm,
                       int M, int N, int K, int lda, int ldb, int ldc,
                       long sAb, long sAh, long sBb, long sBh,
                       long sCb, long sCh, long sBiasB,
                       int inner, float alpha)
{
    const int z  = blockIdx.z;
    const int bo = z / inner, ho = z - bo * inner;
    A  += (long)bo * sAb + (long)ho * sAh;
    Bm += (long)bo * sBb + (long)ho * sBh;
    Cm += (long)bo * sCb + (long)ho * sCh;
    if (bias) bias += (long)bo * sBiasB;

    // 16 k-rows, 128+4 pad: rows 528B (16B aligned), <=2-way STS conflict,
    // conflict-free float4 LDS phases.
    __shared__ __align__(16) float As[16][132];
    __shared__ __align__(16) float Bs[16][132];

    const int m0 = blockIdx.y * 128, n0 = blockIdx.x * 128;
    const int tx = threadIdx.x, ty = threadIdx.y;     // 16 x 16
    const int tid = ty * 16 + tx;
    float acc[8][8] = {};

    for (int k0 = 0; k0 < K; k0 += 16) {
        // ---- load A tile (2048 elems, 8 per thread) ----
        #pragma unroll
        for (int i = 0; i < 8; i++) {
            const int l = tid + i * 256;
            int mm, kk;
            if (TRA == 0) { kk = l & 15; mm = l >> 4; }     // coalesced over gk
            else          { mm = l & 127; kk = l >> 7; }    // coalesced over gm
            const int gm = m0 + mm, gk = k0 + kk;
            float v = 0.f;
            if (gm < M && gk < K)
                v = (TRA == 0) ? A[(long)gm * lda + gk] : A[(long)gk * lda + gm];
            As[kk][mm] = v;
        }
        // ---- load B tile (2048 elems, 8 per thread) ----
        #pragma unroll
        for (int i = 0; i < 8; i++) {
            const int l = tid + i * 256;
            int nn, kk;
            if (TRB == 0) { nn = l & 127; kk = l >> 7; }    // coalesced over gn
            else          { kk = l & 15;  nn = l >> 4; }    // coalesced over gk
            const int gn = n0 + nn, gk = k0 + kk;
            float v = 0.f;
            if (gn < N && gk < K)
                v = (TRB == 0) ? Bm[(long)gk * ldb + gn] : Bm[(long)gn * ldb + gk];
            Bs[kk][nn] = v;
        }
        __syncthreads();

        #pragma unroll
        for (int kk = 0; kk < 16; kk++) {
            // rows: ty*4 + {0..3} and 64 + ty*4 + {0..3}; cols analogous with tx
            const float4 a0 = *(const float4*)&As[kk][ty * 4];
            const float4 a1 = *(const float4*)&As[kk][64 + ty * 4];
            const float4 b0 = *(const float4*)&Bs[kk][tx * 4];
            const float4 b1 = *(const float4*)&Bs[kk][64 + tx * 4];
            const float a[8] = {a0.x, a0.y, a0.z, a0.w, a1.x, a1.y, a1.z, a1.w};
            const float b[8] = {b0.x, b0.y, b0.z, b0.w, b1.x, b1.y, b1.z, b1.w};
            #pragma unroll
            for (int i = 0; i < 8; i++)
                #pragma unroll
                for (int j = 0; j < 8; j++)
                    acc[i][j] += a[i] * b[j];
        }
        __syncthreads();
    }

    // ---- epilogue ----
    #pragma unroll
    for (int i = 0; i < 8; i++) {
        const int gm = m0 + ((i < 4) ? (ty * 4 + i) : (64 + ty * 4 + i - 4));
        if (gm >= M) continue;
        #pragma unroll
        for (int j = 0; j < 8; j++) {
            const int gn = n0 + ((j < 4) ? (tx * 4 + j) : (64 + tx * 4 + j - 4));
            if (gn >= N) continue;
            float v = alpha * acc[i][j];
            if (bias) v += bias[gn];
            if (ACT == ACT_SILU)      v = v / (1.f + expf(-v));
            else if (ACT == ACT_GELU) v = 0.5f * v * (1.f + erff(v * 0.70710678118654752f));
            const long idx = (long)gm * ldc + gn;
            if (BETA) Cm[idx] += v; else Cm[idx] = v;
        }
    }
}

// ---------------- fused flash attention (prefix-causal) ----------------
// qkv: [b][ta][3C] with head h at col h*DH (Q), CC+h*DH (K), 2CC+h*DH (V)
// y  : [b][ta][CC], head h written at col h*DH
// grid: (ceil(TA/64), H, B), block 16x16, dyn smem = (64*64 + 2*64*65)*4 bytes
__global__ void attn_k(const float* __restrict__ qkv, float* __restrict__ y)
{
    extern __shared__ float sm[];
    float* Qs = sm;                 // [64][64]  Qs[i][d]
    float* Ks = sm + 64*64;         // [64][65]  Ks[j][d], reused as Vs[j][d]
    float* Ps = Ks + 64*65;         // [64][65]  Ps[i][j]

    const int b = blockIdx.z, h = blockIdx.y;
    const int q0 = blockIdx.x * 64;
    const int tx = threadIdx.x, ty = threadIdx.y;
    const int tid = ty * 16 + tx;

    const float* Qp = qkv + (long)b * TA * 3 * CC + h * DH;
    const float* Kp = Qp + CC;
    const float* Vp = Qp + 2 * CC;

    // load Q tile
    #pragma unroll
    for (int r = 0; r < 16; r++) {
        const int l = tid + r * 256;
        const int i = l >> 6, d = l & 63;
        const int gi = q0 + i;
        Qs[i * 64 + d] = (gi < TA) ? Qp[(long)gi * 3 * CC + d] : 0.f;
    }

    float m_i[4], l_i[4], o[4][4];
    #pragma unroll
    for (int i = 0; i < 4; i++) {
        m_i[i] = -INFINITY; l_i[i] = 0.f;
        #pragma unroll
        for (int j = 0; j < 4; j++) o[i][j] = 0.f;
    }

    // q-tile 0 contains the free-prefix rows (attend everything);
    // all other tiles are purely causal -> truncate K loop at the diagonal.
    const int kmax = (q0 == 0) ? TA : min(TA, q0 + 64);

    for (int k0 = 0; k0 < kmax; k0 += 64) {
        __syncthreads();            // previous PV finished reading Ks/Ps
        // load K tile
        #pragma unroll
        for (int r = 0; r < 16; r++) {
            const int l = tid + r * 256;
            const int j = l >> 6, d = l & 63;
            const int gj = k0 + j;
            Ks[j * 65 + d] = (gj < TA) ? Kp[(long)gj * 3 * CC + d] : 0.f;
        }
        __syncthreads();

        // S = Q @ K^T (4x4 per thread)
        float s[4][4] = {};
        #pragma unroll
        for (int d = 0; d < 64; d++) {
            float a[4], bb[4];
            #pragma unroll
            for (int i = 0; i < 4; i++) a[i]  = Qs[(ty * 4 + i) * 64 + d];
            #pragma unroll
            for (int j = 0; j < 4; j++) bb[j] = Ks[(tx * 4 + j) * 65 + d];
            #pragma unroll
            for (int i = 0; i < 4; i++)
                #pragma unroll
                for (int j = 0; j < 4; j++)
                    s[i][j] += a[i] * bb[j];
        }

        // mask + scale, online softmax update
        #pragma unroll
        for (int i = 0; i < 4; i++) {
            const int gi = q0 + ty * 4 + i;
            float tm = -INFINITY;
            #pragma unroll
            for (int j = 0; j < 4; j++) {
                const int gj = k0 + tx * 4 + j;
                const bool valid = (gj < TA) && (gi < TA) && (gi < PREFIX || gj <= gi);
                s[i][j] = valid ? s[i][j] * 0.125f : -INFINITY;
                tm = fmaxf(tm, s[i][j]);
            }
            // row max across the 16 lanes sharing this row (width-16 groups)
            #pragma unroll
            for (int off = 8; off > 0; off >>= 1)
                tm = fmaxf(tm, __shfl_xor_sync(0xffffffffu, tm, off, 16));
            const float newm = fmaxf(m_i[i], tm);
            const float alpha = __expf(m_i[i] - newm);   // first tile: exp(-inf)=0
            float rs = 0.f;
            #pragma unroll
            for (int j = 0; j < 4; j++) {
                const float p = __expf(s[i][j] - newm);  // masked -> 0
                s[i][j] = p;
                rs += p;
            }
            #pragma unroll
            for (int off = 8; off > 0; off >>= 1)
                rs += __shfl_xor_sync(0xffffffffu, rs, off, 16);
            l_i[i] = l_i[i] * alpha + rs;
            m_i[i] = newm;
            #pragma unroll
            for (int j = 0; j < 4; j++) o[i][j] *= alpha;
            // stash P
            #pragma unroll
            for (int j = 0; j < 4; j++)
                Ps[(ty * 4 + i) * 65 + tx * 4 + j] = s[i][j];
        }
        __syncthreads();            // Ps written, Ks free

        // load V tile into Ks buffer
        #pragma unroll
        for (int r = 0; r < 16; r++) {
            const int l = tid + r * 256;
            const int j = l >> 6, d = l & 63;
            const int gj = k0 + j;
            Ks[j * 65 + d] = (gj < TA) ? Vp[(long)gj * 3 * CC + d] : 0.f;
        }
        __syncthreads();

        // O += P @ V
        #pragma unroll
        for (int jj = 0; jj < 64; jj++) {
            float a[4], bb[4];
            #pragma unroll
            for (int i = 0; i < 4; i++) a[i]  = Ps[(ty * 4 + i) * 65 + jj];
            #pragma unroll
            for (int d = 0; d < 4; d++) bb[d] = Ks[jj * 65 + tx * 4 + d];
            #pragma unroll
            for (int i = 0; i < 4; i++)
                #pragma unroll
                for (int d = 0; d < 4; d++)
                    o[i][d] += a[i] * bb[d];
        }
    }

    // normalize + store
    #pragma unroll
    for (int i = 0; i < 4; i++) {
        const int gi = q0 + ty * 4 + i;
        if (gi >= TA) continue;
        const float inv = 1.f / l_i[i];
        #pragma unroll
        for (int d = 0; d < 4; d++)
            y[(long)b * TA * CC + (long)gi * CC + h * DH + tx * 4 + d] = o[i][d] * inv;
    }
}

// ---------------- layernorm ----------------
__global__ void ln_k(const float* __restrict__ x, const float* __restrict__ w,
                     const float* __restrict__ b, float* __restrict__ out)
{
    const long r = blockIdx.x;
    const float* xr = x + r * CC;
    __shared__ float red[256];
    float s = 0.f;
    for (int c = threadIdx.x; c < CC; c += 256) s += xr[c];
    red[threadIdx.x] = s; __syncthreads();
    for (int o = 128; o > 0; o >>= 1) { if (threadIdx.x < o) red[threadIdx.x] += red[threadIdx.x + o]; __syncthreads(); }
    const float mu = red[0] / CC;
    __syncthreads();
    float v = 0.f;
    for (int c = threadIdx.x; c < CC; c += 256) { const float d = xr[c] - mu; v += d * d; }
    red[threadIdx.x] = v; __syncthreads();
    for (int o = 128; o > 0; o >>= 1) { if (threadIdx.x < o) red[threadIdx.x] += red[threadIdx.x + o]; __syncthreads(); }
    const float inv = rsqrtf(red[0] / CC + 1e-5f);
    for (int c = threadIdx.x; c < CC; c += 256)
        out[r * CC + c] = (xr[c] - mu) * inv * w[c] + b[c];
}

// ---------------- small helpers ----------------
__global__ void pool_k(const float* __restrict__ mem, float* __restrict__ pooled)
{
    const int idx = blockIdx.x * 256 + threadIdx.x;
    if (idx >= BB * MM * CC) return;
    const int c = idx % CC, m = (idx / CC) % MM, b = idx / (CC * MM);
    const float* p = mem + ((long)b * TT + m * (TT / MM)) * CC + c;
    float s = 0.f;
    #pragma unroll 4
    for (int j = 0; j < TT / MM; j++) s += p[(long)j * CC];
    pooled[idx] = s * (1.f / (TT / MM));
}

__global__ void fill_xa_k(const float* __restrict__ x, const float* __restrict__ persist,
                          float* __restrict__ xa)
{
    const long idx = blockIdx.x * 256L + threadIdx.x;
    if (idx >= (long)BB * TA * CC) return;
    const int c = (int)(idx % CC);
    const long rc = idx / CC;
    const int t = (int)(rc % TA);
    const int b = (int)(rc / TA);
    if (t < MM) return;
    if (t < PREFIX) xa[idx] = persist[(t - MM) * CC + c];
    else            xa[idx] = x[((long)b * TT + (t - PREFIX)) * CC + c];
}

__global__ void copy_out_k(const float* __restrict__ xa, float* __restrict__ out)
{
    const long idx = blockIdx.x * 256L + threadIdx.x;
    if (idx >= (long)BB * TT * CC) return;
    const int c = (int)(idx % CC);
    const long rc = idx / CC;
    const int t = (int)(rc % TT);
    const int b = (int)(rc / TT);
    out[idx] = xa[((long)b * TA + PREFIX + t) * CC + c];
}

__global__ void silu_k(const float* __restrict__ pre, float* __restrict__ hh, long n)
{
    const long i = blockIdx.x * 256L + threadIdx.x;
    if (i >= n) return;
    const float z = pre[i];
    hh[i] = z / (1.f + expf(-z));
}

__global__ void dpred_k(float* __restrict__ pred, const float* __restrict__ vals, float coef, long n)
{
    const long i = blockIdx.x * 256L + threadIdx.x;
    if (i >= n) return;
    pred[i] = coef * (pred[i] - vals[i]);
}

__global__ void dpre_k(float* __restrict__ dhh, const float* __restrict__ pre, long n)
{
    const long i = blockIdx.x * 256L + threadIdx.x;
    if (i >= n) return;
    const float z = pre[i];
    const float s = 1.f / (1.f + expf(-z));
    dhh[i] *= s * (1.f + z * (1.f - s));
}

__global__ void colsum_k(const float* __restrict__ a, float* __restrict__ out, int rows, int cols)
{
    const int idx = blockIdx.x * 256 + threadIdx.x;
    if (idx >= BB * cols) return;
    const int c = idx % cols, b = idx / cols;
    const float* p = a + (long)b * rows * cols + c;
    float s = 0.f;
    for (int t = 0; t < rows; t++) s += p[(long)t * cols];
    out[idx] = s;
}

__global__ void update_k(const float* __restrict__ w, const float* __restrict__ mom,
                         const float* __restrict__ g,
                         float* __restrict__ nw, float* __restrict__ nmom, long n)
{
    const long i = blockIdx.x * 256L + threadIdx.x;
    if (i >= n) return;
    const float nm = MUc * mom[i] + g[i];
    nmom[i] = nm;
    nw[i] = (1.f - DECAY) * w[i] - LR * nm;
}

// ---------------- host orchestration ----------------
static inline dim3 gblk(int N, int M, int Z) { return dim3((N + 127) / 128, (M + 127) / 128, Z); }

extern "C" void kernel_launch(void* const* d_in, const int* in_sizes, int n_in,
                              void* d_out, int out_size)
{
    const float* x        = (const float*)d_in[0];
    const float* persist  = (const float*)d_in[1];
    const float* ln1_w    = (const float*)d_in[2];
    const float* ln1_b    = (const float*)d_in[3];
    const float* ln2_w    = (const float*)d_in[4];
    const float* ln2_b    = (const float*)d_in[5];
    const float* attn_w   = (const float*)d_in[6];
    const float* attn_b   = (const float*)d_in[7];
    const float* aproj_w  = (const float*)d_in[8];
    const float* aproj_b  = (const float*)d_in[9];
    const float* fc_w     = (const float*)d_in[10];
    const float* fc_b     = (const float*)d_in[11];
    const float* mproj_w  = (const float*)d_in[12];
    const float* mproj_b  = (const float*)d_in[13];
    const float* q_w      = (const float*)d_in[14];
    const float* q_b      = (const float*)d_in[15];
    const float* k_w      = (const float*)d_in[16];
    const float* k_b      = (const float*)d_in[17];
    const float* v_w      = (const float*)d_in[18];
    const float* v_b      = (const float*)d_in[19];
    const float* o_w      = (const float*)d_in[20];
    const float* o_b      = (const float*)d_in[21];
    const float* mem_w0   = (const float*)d_in[22];
    const float* mem_b0   = (const float*)d_in[23];
    const float* mem_w1   = (const float*)d_in[24];
    const float* mem_b1   = (const float*)d_in[25];
    const float* mom_w0   = (const float*)d_in[26];
    const float* mom_b0   = (const float*)d_in[27];
    const float* mom_w1   = (const float*)d_in[28];
    const float* mom_b1   = (const float*)d_in[29];
    float* out = (float*)d_out;

    float *bufA, *bufB, *bufC, *x1, *x2, *x3, *pool, *xa, *hln, *qkv, *fc, *y,
          *gw0, *gw1, *gb0, *gb1;
    cudaGetSymbolAddress((void**)&bufA, g_a);
    cudaGetSymbolAddress((void**)&bufB, g_b);
    cudaGetSymbolAddress((void**)&bufC, g_c);
    cudaGetSymbolAddress((void**)&x1,   g_x1);
    cudaGetSymbolAddress((void**)&x2,   g_x2);
    cudaGetSymbolAddress((void**)&x3,   g_x3);
    cudaGetSymbolAddress((void**)&pool, g_pool);
    cudaGetSymbolAddress((void**)&xa,   g_xa);
    cudaGetSymbolAddress((void**)&hln,  g_hln);
    cudaGetSymbolAddress((void**)&qkv,  g_qkv);
    cudaGetSymbolAddress((void**)&fc,   g_fc);
    cudaGetSymbolAddress((void**)&y,    g_y);
    cudaGetSymbolAddress((void**)&gw0,  g_gw0);
    cudaGetSymbolAddress((void**)&gw1,  g_gw1);
    cudaGetSymbolAddress((void**)&gb0,  g_gb0);
    cudaGetSymbolAddress((void**)&gb1,  g_gb1);

    const int ATTN_SMEM = (64*64 + 2*64*65) * (int)sizeof(float);   // 49,664 B
    cudaFuncSetAttribute(attn_k, cudaFuncAttributeMaxDynamicSharedMemorySize, ATTN_SMEM);

    const dim3 th(16, 16);
    const long sTC  = (long)TT * CC;
    const long sTH  = (long)TT * HID;
    const long sAC  = (long)TA * CC;
    const long sA3C = (long)TA * 3 * CC;
    const long sA4C = (long)TA * 4 * CC;
    const long sWH0 = (long)HID * CC;
    const long sWH1 = (long)CC * HID;

    // 1) q = x @ q_w.T + q_b           -> x1
    gemm_k<0,1,ACT_NONE,0><<<gblk(CC, TT, BB), th>>>(x, q_w, q_b, x1,
        TT, CC, CC, CC, CC, CC, sTC,0, 0,0, sTC,0, 0, 1, 1.f);
    // 2) h = silu(q @ w0_b.T + b0_b)   -> bufA
    gemm_k<0,1,ACT_SILU,0><<<gblk(HID, TT, BB), th>>>(x1, mem_w0, mem_b0, bufA,
        TT, HID, CC, CC, CC, HID, sTC,0, sWH0,0, sTH,0, HID, 1, 1.f);
    // 3) mem = h @ w1_b.T + b1_b       -> x2
    gemm_k<0,1,ACT_NONE,0><<<gblk(CC, TT, BB), th>>>(bufA, mem_w1, mem_b1, x2,
        TT, CC, HID, HID, HID, CC, sTH,0, sWH1,0, sTC,0, CC, 1, 1.f);
    // 4) pooled = segment mean
    pool_k<<<(BB*MM*CC + 255)/256, 256>>>(x2, pool);
    // 5) retrieved -> xa rows [0,16)
    gemm_k<0,1,ACT_NONE,0><<<gblk(CC, MM, BB), th>>>(pool, o_w, o_b, xa,
        MM, CC, CC, CC, CC, CC, (long)MM*CC,0, 0,0, sAC,0, 0, 1, 1.f);
    // 6) persist + x -> xa rows [16,ta)
    fill_xa_k<<<(int)(((long)BB*TA*CC + 255)/256), 256>>>(x, persist, xa);
    // 7) hln = LN1(xa)
    ln_k<<<BB*TA, 256>>>(xa, ln1_w, ln1_b, hln);
    // 8) qkv = hln @ attn_w.T + attn_b
    gemm_k<0,1,ACT_NONE,0><<<gblk(3*CC, TA, BB), th>>>(hln, attn_w, attn_b, qkv,
        TA, 3*CC, CC, CC, CC, 3*CC, sAC,0, 0,0, sA3C,0, 0, 1, 1.f);
    // 9-11) fused flash attention -> y
    attn_k<<<dim3((TA + 63)/64, HH, BB), th, ATTN_SMEM>>>(qkv, y);
    // 12) xa += y @ aproj_w.T + aproj_b
    gemm_k<0,1,ACT_NONE,1><<<gblk(CC, TA, BB), th>>>(y, aproj_w, aproj_b, xa,
        TA, CC, CC, CC, CC, CC, sAC,0, 0,0, sAC,0, 0, 1, 1.f);
    // 13) h2 = LN2(xa)  (reuse hln)
    ln_k<<<BB*TA, 256>>>(xa, ln2_w, ln2_b, hln);
    // 14) fc = gelu(h2 @ fc_w.T + fc_b)
    gemm_k<0,1,ACT_GELU,0><<<gblk(4*CC, TA, BB), th>>>(hln, fc_w, fc_b, fc,
        TA, 4*CC, CC, CC, CC, 4*CC, sAC,0, 0,0, sA4C,0, 0, 1, 1.f);
    // 15) xa += fc @ mproj_w.T + mproj_b
    gemm_k<0,1,ACT_NONE,1><<<gblk(CC, TA, BB), th>>>(fc, mproj_w, mproj_b, xa,
        TA, CC, 4*CC, 4*CC, 4*CC, CC, sA4C,0, 0,0, sAC,0, 0, 1, 1.f);
    // 16) out = xa[:, prefix:]
    copy_out_k<<<(int)(((long)BB*TT*CC + 255)/256), 256>>>(xa, out);
    // 17/18) keys -> x2, vals -> x3
    gemm_k<0,1,ACT_NONE,0><<<gblk(CC, TT, BB), th>>>(xa + PREFIX*CC, k_w, k_b, x2,
        TT, CC, CC, CC, CC, CC, sAC,0, 0,0, sTC,0, 0, 1, 1.f);
    gemm_k<0,1,ACT_NONE,0><<<gblk(CC, TT, BB), th>>>(xa + PREFIX*CC, v_w, v_b, x3,
        TT, CC, CC, CC, CC, CC, sAC,0, 0,0, sTC,0, 0, 1, 1.f);
    // 19) pre = keys @ w0.T + b0       -> bufA
    gemm_k<0,1,ACT_NONE,0><<<gblk(HID, TT, BB), th>>>(x2, mem_w0, mem_b0, bufA,
        TT, HID, CC, CC, CC, HID, sTC,0, sWH0,0, sTH,0, HID, 1, 1.f);
    // 20) hh = silu(pre)               -> bufB
    silu_k<<<(int)(((long)BB*TT*HID + 255)/256), 256>>>(bufA, bufB, (long)BB*TT*HID);
    // 21) pred = hh @ w1.T + b1        -> x1
    gemm_k<0,1,ACT_NONE,0><<<gblk(CC, TT, BB), th>>>(bufB, mem_w1, mem_b1, x1,
        TT, CC, HID, HID, HID, CC, sTH,0, sWH1,0, sTC,0, CC, 1, 1.f);
    // 22) d_pred = 2/(T*C) * (pred - vals), in place in x1
    dpred_k<<<(int)(((long)BB*TT*CC + 255)/256), 256>>>(x1, x3,
        2.f / (float)(TT * CC), (long)BB*TT*CC);
    // 23) g_w1 = d_pred.T @ hh   (TN)
    gemm_k<1,0,ACT_NONE,0><<<gblk(HID, CC, BB), th>>>(x1, bufB, nullptr, gw1,
        CC, HID, TT, CC, HID, HID, sTC,0, sTH,0, sWH1,0, 0, 1, 1.f);
    // 24) g_b1 = colsum(d_pred)
    colsum_k<<<(BB*CC + 255)/256, 256>>>(x1, gb1, TT, CC);
    // 25) d_hh = d_pred @ w1   (NN)    -> bufC
    gemm_k<0,0,ACT_NONE,0><<<gblk(HID, TT, BB), th>>>(x1, mem_w1, nullptr, bufC,
        TT, HID, CC, CC, HID, HID, sTC,0, sWH1,0, sTH,0, 0, 1, 1.f);
    // 26) d_pre = d_hh * silu'(pre), in place in bufC
    dpre_k<<<(int)(((long)BB*TT*HID + 255)/256), 256>>>(bufC, bufA, (long)BB*TT*HID);
    // 27) g_w0 = d_pre.T @ keys   (TN)
    gemm_k<1,0,ACT_NONE,0><<<gblk(CC, HID, BB), th>>>(bufC, x2, nullptr, gw0,
        HID, CC, TT, HID, CC, CC, sTH,0, sTC,0, sWH0,0, 0, 1, 1.f);
    // 28) g_b0 = colsum(d_pre)
    colsum_k<<<(BB*HID + 255)/256, 256>>>(bufC, gb0, TT, HID);

    // 29) momentum + decay updates -> output segments
    const long n_out = (long)BB*TT*CC;
    const long n_w0  = (long)BB*HID*CC;
    const long n_b0  = (long)BB*HID;
    const long n_w1  = (long)BB*CC*HID;
    const long n_b1  = (long)BB*CC;
    float* o_nw0 = out + n_out;
    float* o_nb0 = o_nw0 + n_w0;
    float* o_nw1 = o_nb0 + n_b0;
    float* o_nb1 = o_nw1 + n_w1;
    float* o_mw0 = o_nb1 + n_b1;
    float* o_mb0 = o_mw0 + n_w0;
    float* o_mw1 = o_mb0 + n_b0;
    float* o_mb1 = o_mw1 + n_w1;
    update_k<<<(int)((n_w0 + 255)/256), 256>>>(mem_w0, mom_w0, gw0, o_nw0, o_mw0, n_w0);
    update_k<<<(int)((n_b0 + 255)/256), 256>>>(mem_b0, mom_b0, gb0, o_nb0, o_mb0, n_b0);
    update_k<<<(int)((n_w1 + 255)/256), 256>>>(mem_w1, mom_w1, gw1, o_nw1, o_mw1, n_w1);
    update_k<<<(int)((n_b1 + 255)/256), 256>>>(mem_b1, mom_b1, gb1, o_nb1, o_mb1, n_b1);
}

// round 8
// speedup vs baseline: 1.1874x; 1.1874x over previous
#include <cuda_runtime.h>
#include <mma.h>
#include <math.h>

using namespace nvcuda;

// ---------------- problem constants ----------------
static constexpr int BB   = 8;
static constexpr int TT   = 1024;
static constexpr int CC   = 768;
static constexpr int HH   = 12;
static constexpr int HID  = 1536;
static constexpr int MM   = 16;
static constexpr int PP   = 4;
static constexpr int PREFIX = MM + PP;          // 20
static constexpr int TA   = TT + PREFIX;        // 1044
static constexpr int DH   = CC / HH;            // 64
static constexpr float LR = 0.01f, MUc = 0.9f, DECAY = 0.001f;

// ---------------- scratch (device globals; allocation-free) ----------------
__device__ float g_a  [BB*TT*HID];   // mem-fwd hidden | bwd pre
__device__ float g_b  [BB*TT*HID];   // bwd hh
__device__ float g_c  [BB*TT*HID];   // bwd d_hh/d_pre
__device__ float g_x1 [BB*TT*CC];    // q proj | d_pred
__device__ float g_x2 [BB*TT*CC];    // mem out | keys
__device__ float g_x3 [BB*TT*CC];    // vals
__device__ float g_pool[BB*MM*CC];
__device__ float g_xa [BB*TA*CC];
__device__ float g_hln[BB*TA*CC];
__device__ float g_qkv[BB*TA*3*CC];
__device__ float g_y  [BB*TA*CC];
__device__ float g_fc [BB*TA*4*CC];
__device__ float g_gw0[BB*HID*CC];
__device__ float g_gw1[BB*CC*HID];
__device__ float g_gb0[BB*HID];
__device__ float g_gb1[BB*CC];

// ---------------- generic batched GEMM (tensor cores, TF32 WMMA) ------------
// C[z] = beta*C[z] + act(alpha * opA(A[z]) @ opB(B[z]) + bias)
// TRA==1 -> use A^T (read A[k*lda+m]); TRB==1 -> x @ W^T (read B[n*ldb+k])
// Tile 128x128, k-step 16 (two k=8 wmma steps). 256 threads = 8 warps,
// each warp owns a 64x32 sub-tile = 4x2 fragments of 16x16.
// smem tiles: As[k][m] (A col-major, m fastest), Bs[k][n] (B row-major).
enum { ACT_NONE = 0, ACT_SILU = 1, ACT_GELU = 2 };

template<int TRA, int TRB, int ACT, int BETA>
__global__ void gemm_k(const float* __restrict__ A, const float* __restrict__ Bm,
                       const float* __restrict__ bias, float* __restrict__ Cm,
                       int M, int N, int K, int lda, int ldb, int ldc,
                       long sAb, long sAh, long sBb, long sBh,
                       long sCb, long sCh, long sBiasB,
                       int inner, float alpha)
{
    const int z  = blockIdx.z;
    const int bo = z / inner, ho = z - bo * inner;
    A  += (long)bo * sAb + (long)ho * sAh;
    Bm += (long)bo * sBb + (long)ho * sBh;
    Cm += (long)bo * sCb + (long)ho * sCh;
    if (bias) bias += (long)bo * sBiasB;

    __shared__ __align__(16) float As[16][132];  // 528B rows (16B multiple)
    __shared__ __align__(16) float Bs[16][132];
    __shared__ __align__(16) float Cs[8][256];   // per-warp 16x16 staging

    const int m0 = blockIdx.y * 128, n0 = blockIdx.x * 128;
    const int tid  = threadIdx.x;
    const int warp = tid >> 5, lane = tid & 31;
    const int wm = (warp >> 2) * 64;   // warp m-offset within tile (0 or 64)
    const int wn = (warp & 3) * 32;    // warp n-offset within tile (0,32,64,96)

    wmma::fragment<wmma::accumulator, 16, 16, 8, float> acc[4][2];
    #pragma unroll
    for (int i = 0; i < 4; i++)
        #pragma unroll
        for (int j = 0; j < 2; j++)
            wmma::fill_fragment(acc[i][j], 0.f);

    for (int k0 = 0; k0 < K; k0 += 16) {
        // ---- load A tile (2048 elems, 8 per thread) -> As[k][m] ----
        #pragma unroll
        for (int i = 0; i < 8; i++) {
            const int l = tid + i * 256;
            int mm, kk;
            if (TRA == 0) { kk = l & 15; mm = l >> 4; }     // coalesced over gk
            else          { mm = l & 127; kk = l >> 7; }    // coalesced over gm
            const int gm = m0 + mm, gk = k0 + kk;
            float v = 0.f;
            if (gm < M && gk < K)
                v = (TRA == 0) ? A[(long)gm * lda + gk] : A[(long)gk * lda + gm];
            As[kk][mm] = v;
        }
        // ---- load B tile (2048 elems, 8 per thread) -> Bs[k][n] ----
        #pragma unroll
        for (int i = 0; i < 8; i++) {
            const int l = tid + i * 256;
            int nn, kk;
            if (TRB == 0) { nn = l & 127; kk = l >> 7; }    // coalesced over gn
            else          { kk = l & 15;  nn = l >> 4; }    // coalesced over gk
            const int gn = n0 + nn, gk = k0 + kk;
            float v = 0.f;
            if (gn < N && gk < K)
                v = (TRB == 0) ? Bm[(long)gk * ldb + gn] : Bm[(long)gn * ldb + gk];
            Bs[kk][nn] = v;
        }
        __syncthreads();

        #pragma unroll
        for (int ks = 0; ks < 16; ks += 8) {
            wmma::fragment<wmma::matrix_a, 16, 16, 8, wmma::precision::tf32,
                           wmma::col_major> af[4];
            wmma::fragment<wmma::matrix_b, 16, 16, 8, wmma::precision::tf32,
                           wmma::row_major> bf[2];
            #pragma unroll
            for (int i = 0; i < 4; i++) {
                wmma::load_matrix_sync(af[i], &As[ks][wm + i * 16], 132);
                #pragma unroll
                for (int t = 0; t < af[i].num_elements; t++)
                    af[i].x[t] = wmma::__float_to_tf32(af[i].x[t]);
            }
            #pragma unroll
            for (int j = 0; j < 2; j++) {
                wmma::load_matrix_sync(bf[j], &Bs[ks][wn + j * 16], 132);
                #pragma unroll
                for (int t = 0; t < bf[j].num_elements; t++)
                    bf[j].x[t] = wmma::__float_to_tf32(bf[j].x[t]);
            }
            #pragma unroll
            for (int i = 0; i < 4; i++)
                #pragma unroll
                for (int j = 0; j < 2; j++)
                    wmma::mma_sync(acc[i][j], af[i], bf[j], acc[i][j]);
        }
        __syncthreads();
    }

    // ---- epilogue: stage each 16x16 fragment, apply alpha/bias/act/beta ----
    #pragma unroll
    for (int i = 0; i < 4; i++) {
        #pragma unroll
        for (int j = 0; j < 2; j++) {
            wmma::store_matrix_sync(&Cs[warp][0], acc[i][j], 16, wmma::mem_row_major);
            __syncwarp();
            const int gmb = m0 + wm + i * 16;
            const int gnb = n0 + wn + j * 16;
            #pragma unroll
            for (int e = 0; e < 8; e++) {
                const int idx2 = lane + e * 32;
                const int r = idx2 >> 4, c = idx2 & 15;
                const int gm = gmb + r, gn = gnb + c;
                if (gm < M && gn < N) {
                    float v = alpha * Cs[warp][idx2];
                    if (bias) v += bias[gn];
                    if (ACT == ACT_SILU)      v = v / (1.f + expf(-v));
                    else if (ACT == ACT_GELU) v = 0.5f * v * (1.f + erff(v * 0.70710678118654752f));
                    const long oidx = (long)gm * ldc + gn;
                    if (BETA) Cm[oidx] += v; else Cm[oidx] = v;
                }
            }
            __syncwarp();
        }
    }
}

// ---------------- fused flash attention (prefix-causal) ----------------
// qkv: [b][ta][3C] with head h at col h*DH (Q), CC+h*DH (K), 2CC+h*DH (V)
// y  : [b][ta][CC], head h written at col h*DH
// grid: (ceil(TA/64), H, B), block 16x16, dyn smem = (64*64 + 2*64*65)*4 bytes
__global__ void attn_k(const float* __restrict__ qkv, float* __restrict__ y)
{
    extern __shared__ float sm[];
    float* Qs = sm;                 // [64][64]  Qs[i][d]
    float* Ks = sm + 64*64;         // [64][65]  Ks[j][d], reused as Vs[j][d]
    float* Ps = Ks + 64*65;         // [64][65]  Ps[i][j]

    const int b = blockIdx.z, h = blockIdx.y;
    const int q0 = blockIdx.x * 64;
    const int tx = threadIdx.x, ty = threadIdx.y;
    const int tid = ty * 16 + tx;

    const float* Qp = qkv + (long)b * TA * 3 * CC + h * DH;
    const float* Kp = Qp + CC;
    const float* Vp = Qp + 2 * CC;

    // load Q tile
    #pragma unroll
    for (int r = 0; r < 16; r++) {
        const int l = tid + r * 256;
        const int i = l >> 6, d = l & 63;
        const int gi = q0 + i;
        Qs[i * 64 + d] = (gi < TA) ? Qp[(long)gi * 3 * CC + d] : 0.f;
    }

    float m_i[4], l_i[4], o[4][4];
    #pragma unroll
    for (int i = 0; i < 4; i++) {
        m_i[i] = -INFINITY; l_i[i] = 0.f;
        #pragma unroll
        for (int j = 0; j < 4; j++) o[i][j] = 0.f;
    }

    const int kmax = (q0 == 0) ? TA : min(TA, q0 + 64);

    for (int k0 = 0; k0 < kmax; k0 += 64) {
        __syncthreads();
        #pragma unroll
        for (int r = 0; r < 16; r++) {
            const int l = tid + r * 256;
            const int j = l >> 6, d = l & 63;
            const int gj = k0 + j;
            Ks[j * 65 + d] = (gj < TA) ? Kp[(long)gj * 3 * CC + d] : 0.f;
        }
        __syncthreads();

        float s[4][4] = {};
        #pragma unroll
        for (int d = 0; d < 64; d++) {
            float a[4], bb[4];
            #pragma unroll
            for (int i = 0; i < 4; i++) a[i]  = Qs[(ty * 4 + i) * 64 + d];
            #pragma unroll
            for (int j = 0; j < 4; j++) bb[j] = Ks[(tx * 4 + j) * 65 + d];
            #pragma unroll
            for (int i = 0; i < 4; i++)
                #pragma unroll
                for (int j = 0; j < 4; j++)
                    s[i][j] += a[i] * bb[j];
        }

        #pragma unroll
        for (int i = 0; i < 4; i++) {
            const int gi = q0 + ty * 4 + i;
            float tm = -INFINITY;
            #pragma unroll
            for (int j = 0; j < 4; j++) {
                const int gj = k0 + tx * 4 + j;
                const bool valid = (gj < TA) && (gi < TA) && (gi < PREFIX || gj <= gi);
                s[i][j] = valid ? s[i][j] * 0.125f : -INFINITY;
                tm = fmaxf(tm, s[i][j]);
            }
            #pragma unroll
            for (int off = 8; off > 0; off >>= 1)
                tm = fmaxf(tm, __shfl_xor_sync(0xffffffffu, tm, off, 16));
            const float newm = fmaxf(m_i[i], tm);
            const float alpha = __expf(m_i[i] - newm);
            float rs = 0.f;
            #pragma unroll
            for (int j = 0; j < 4; j++) {
                const float p = __expf(s[i][j] - newm);
                s[i][j] = p;
                rs += p;
            }
            #pragma unroll
            for (int off = 8; off > 0; off >>= 1)
                rs += __shfl_xor_sync(0xffffffffu, rs, off, 16);
            l_i[i] = l_i[i] * alpha + rs;
            m_i[i] = newm;
            #pragma unroll
            for (int j = 0; j < 4; j++) o[i][j] *= alpha;
            #pragma unroll
            for (int j = 0; j < 4; j++)
                Ps[(ty * 4 + i) * 65 + tx * 4 + j] = s[i][j];
        }
        __syncthreads();

        #pragma unroll
        for (int r = 0; r < 16; r++) {
            const int l = tid + r * 256;
            const int j = l >> 6, d = l & 63;
            const int gj = k0 + j;
            Ks[j * 65 + d] = (gj < TA) ? Vp[(long)gj * 3 * CC + d] : 0.f;
        }
        __syncthreads();

        #pragma unroll
        for (int jj = 0; jj < 64; jj++) {
            float a[4], bb[4];
            #pragma unroll
            for (int i = 0; i < 4; i++) a[i]  = Ps[(ty * 4 + i) * 65 + jj];
            #pragma unroll
            for (int d = 0; d < 4; d++) bb[d] = Ks[jj * 65 + tx * 4 + d];
            #pragma unroll
            for (int i = 0; i < 4; i++)
                #pragma unroll
                for (int d = 0; d < 4; d++)
                    o[i][d] += a[i] * bb[d];
        }
    }

    #pragma unroll
    for (int i = 0; i < 4; i++) {
        const int gi = q0 + ty * 4 + i;
        if (gi >= TA) continue;
        const float inv = 1.f / l_i[i];
        #pragma unroll
        for (int d = 0; d < 4; d++)
            y[(long)b * TA * CC + (long)gi * CC + h * DH + tx * 4 + d] = o[i][d] * inv;
    }
}

// ---------------- layernorm ----------------
__global__ void ln_k(const float* __restrict__ x, const float* __restrict__ w,
                     const float* __restrict__ b, float* __restrict__ out)
{
    const long r = blockIdx.x;
    const float* xr = x + r * CC;
    __shared__ float red[256];
    float s = 0.f;
    for (int c = threadIdx.x; c < CC; c += 256) s += xr[c];
    red[threadIdx.x] = s; __syncthreads();
    for (int o = 128; o > 0; o >>= 1) { if (threadIdx.x < o) red[threadIdx.x] += red[threadIdx.x + o]; __syncthreads(); }
    const float mu = red[0] / CC;
    __syncthreads();
    float v = 0.f;
    for (int c = threadIdx.x; c < CC; c += 256) { const float d = xr[c] - mu; v += d * d; }
    red[threadIdx.x] = v; __syncthreads();
    for (int o = 128; o > 0; o >>= 1) { if (threadIdx.x < o) red[threadIdx.x] += red[threadIdx.x + o]; __syncthreads(); }
    const float inv = rsqrtf(red[0] / CC + 1e-5f);
    for (int c = threadIdx.x; c < CC; c += 256)
        out[r * CC + c] = (xr[c] - mu) * inv * w[c] + b[c];
}

// ---------------- small helpers ----------------
__global__ void pool_k(const float* __restrict__ mem, float* __restrict__ pooled)
{
    const int idx = blockIdx.x * 256 + threadIdx.x;
    if (idx >= BB * MM * CC) return;
    const int c = idx % CC, m = (idx / CC) % MM, b = idx / (CC * MM);
    const float* p = mem + ((long)b * TT + m * (TT / MM)) * CC + c;
    float s = 0.f;
    #pragma unroll 4
    for (int j = 0; j < TT / MM; j++) s += p[(long)j * CC];
    pooled[idx] = s * (1.f / (TT / MM));
}

__global__ void fill_xa_k(const float* __restrict__ x, const float* __restrict__ persist,
                          float* __restrict__ xa)
{
    const long idx = blockIdx.x * 256L + threadIdx.x;
    if (idx >= (long)BB * TA * CC) return;
    const int c = (int)(idx % CC);
    const long rc = idx / CC;
    const int t = (int)(rc % TA);
    const int b = (int)(rc / TA);
    if (t < MM) return;
    if (t < PREFIX) xa[idx] = persist[(t - MM) * CC + c];
    else            xa[idx] = x[((long)b * TT + (t - PREFIX)) * CC + c];
}

__global__ void copy_out_k(const float* __restrict__ xa, float* __restrict__ out)
{
    const long idx = blockIdx.x * 256L + threadIdx.x;
    if (idx >= (long)BB * TT * CC) return;
    const int c = (int)(idx % CC);
    const long rc = idx / CC;
    const int t = (int)(rc % TT);
    const int b = (int)(rc / TT);
    out[idx] = xa[((long)b * TA + PREFIX + t) * CC + c];
}

__global__ void silu_k(const float* __restrict__ pre, float* __restrict__ hh, long n)
{
    const long i = blockIdx.x * 256L + threadIdx.x;
    if (i >= n) return;
    const float z = pre[i];
    hh[i] = z / (1.f + expf(-z));
}

__global__ void dpred_k(float* __restrict__ pred, const float* __restrict__ vals, float coef, long n)
{
    const long i = blockIdx.x * 256L + threadIdx.x;
    if (i >= n) return;
    pred[i] = coef * (pred[i] - vals[i]);
}

__global__ void dpre_k(float* __restrict__ dhh, const float* __restrict__ pre, long n)
{
    const long i = blockIdx.x * 256L + threadIdx.x;
    if (i >= n) return;
    const float z = pre[i];
    const float s = 1.f / (1.f + expf(-z));
    dhh[i] *= s * (1.f + z * (1.f - s));
}

__global__ void colsum_k(const float* __restrict__ a, float* __restrict__ out, int rows, int cols)
{
    const int idx = blockIdx.x * 256 + threadIdx.x;
    if (idx >= BB * cols) return;
    const int c = idx % cols, b = idx / cols;
    const float* p = a + (long)b * rows * cols + c;
    float s = 0.f;
    for (int t = 0; t < rows; t++) s += p[(long)t * cols];
    out[idx] = s;
}

__global__ void update_k(const float* __restrict__ w, const float* __restrict__ mom,
                         const float* __restrict__ g,
                         float* __restrict__ nw, float* __restrict__ nmom, long n)
{
    const long i = blockIdx.x * 256L + threadIdx.x;
    if (i >= n) return;
    const float nm = MUc * mom[i] + g[i];
    nmom[i] = nm;
    nw[i] = (1.f - DECAY) * w[i] - LR * nm;
}

// ---------------- host orchestration ----------------
static inline dim3 gblk(int N, int M, int Z) { return dim3((N + 127) / 128, (M + 127) / 128, Z); }

extern "C" void kernel_launch(void* const* d_in, const int* in_sizes, int n_in,
                              void* d_out, int out_size)
{
    const float* x        = (const float*)d_in[0];
    const float* persist  = (const float*)d_in[1];
    const float* ln1_w    = (const float*)d_in[2];
    const float* ln1_b    = (const float*)d_in[3];
    const float* ln2_w    = (const float*)d_in[4];
    const float* ln2_b    = (const float*)d_in[5];
    const float* attn_w   = (const float*)d_in[6];
    const float* attn_b   = (const float*)d_in[7];
    const float* aproj_w  = (const float*)d_in[8];
    const float* aproj_b  = (const float*)d_in[9];
    const float* fc_w     = (const float*)d_in[10];
    const float* fc_b     = (const float*)d_in[11];
    const float* mproj_w  = (const float*)d_in[12];
    const float* mproj_b  = (const float*)d_in[13];
    const float* q_w      = (const float*)d_in[14];
    const float* q_b      = (const float*)d_in[15];
    const float* k_w      = (const float*)d_in[16];
    const float* k_b      = (const float*)d_in[17];
    const float* v_w      = (const float*)d_in[18];
    const float* v_b      = (const float*)d_in[19];
    const float* o_w      = (const float*)d_in[20];
    const float* o_b      = (const float*)d_in[21];
    const float* mem_w0   = (const float*)d_in[22];
    const float* mem_b0   = (const float*)d_in[23];
    const float* mem_w1   = (const float*)d_in[24];
    const float* mem_b1   = (const float*)d_in[25];
    const float* mom_w0   = (const float*)d_in[26];
    const float* mom_b0   = (const float*)d_in[27];
    const float* mom_w1   = (const float*)d_in[28];
    const float* mom_b1   = (const float*)d_in[29];
    float* out = (float*)d_out;

    float *bufA, *bufB, *bufC, *x1, *x2, *x3, *pool, *xa, *hln, *qkv, *fc, *y,
          *gw0, *gw1, *gb0, *gb1;
    cudaGetSymbolAddress((void**)&bufA, g_a);
    cudaGetSymbolAddress((void**)&bufB, g_b);
    cudaGetSymbolAddress((void**)&bufC, g_c);
    cudaGetSymbolAddress((void**)&x1,   g_x1);
    cudaGetSymbolAddress((void**)&x2,   g_x2);
    cudaGetSymbolAddress((void**)&x3,   g_x3);
    cudaGetSymbolAddress((void**)&pool, g_pool);
    cudaGetSymbolAddress((void**)&xa,   g_xa);
    cudaGetSymbolAddress((void**)&hln,  g_hln);
    cudaGetSymbolAddress((void**)&qkv,  g_qkv);
    cudaGetSymbolAddress((void**)&fc,   g_fc);
    cudaGetSymbolAddress((void**)&y,    g_y);
    cudaGetSymbolAddress((void**)&gw0,  g_gw0);
    cudaGetSymbolAddress((void**)&gw1,  g_gw1);
    cudaGetSymbolAddress((void**)&gb0,  g_gb0);
    cudaGetSymbolAddress((void**)&gb1,  g_gb1);

    const int ATTN_SMEM = (64*64 + 2*64*65) * (int)sizeof(float);   // 49,664 B
    cudaFuncSetAttribute(attn_k, cudaFuncAttributeMaxDynamicSharedMemorySize, ATTN_SMEM);

    const dim3 thG(256);          // gemm_k: 8 warps
    const dim3 thA(16, 16);       // attn_k
    const long sTC  = (long)TT * CC;
    const long sTH  = (long)TT * HID;
    const long sAC  = (long)TA * CC;
    const long sA3C = (long)TA * 3 * CC;
    const long sA4C = (long)TA * 4 * CC;
    const long sWH0 = (long)HID * CC;
    const long sWH1 = (long)CC * HID;

    // 1) q = x @ q_w.T + q_b           -> x1
    gemm_k<0,1,ACT_NONE,0><<<gblk(CC, TT, BB), thG>>>(x, q_w, q_b, x1,
        TT, CC, CC, CC, CC, CC, sTC,0, 0,0, sTC,0, 0, 1, 1.f);
    // 2) h = silu(q @ w0_b.T + b0_b)   -> bufA
    gemm_k<0,1,ACT_SILU,0><<<gblk(HID, TT, BB), thG>>>(x1, mem_w0, mem_b0, bufA,
        TT, HID, CC, CC, CC, HID, sTC,0, sWH0,0, sTH,0, HID, 1, 1.f);
    // 3) mem = h @ w1_b.T + b1_b       -> x2
    gemm_k<0,1,ACT_NONE,0><<<gblk(CC, TT, BB), thG>>>(bufA, mem_w1, mem_b1, x2,
        TT, CC, HID, HID, HID, CC, sTH,0, sWH1,0, sTC,0, CC, 1, 1.f);
    // 4) pooled = segment mean
    pool_k<<<(BB*MM*CC + 255)/256, 256>>>(x2, pool);
    // 5) retrieved -> xa rows [0,16)
    gemm_k<0,1,ACT_NONE,0><<<gblk(CC, MM, BB), thG>>>(pool, o_w, o_b, xa,
        MM, CC, CC, CC, CC, CC, (long)MM*CC,0, 0,0, sAC,0, 0, 1, 1.f);
    // 6) persist + x -> xa rows [16,ta)
    fill_xa_k<<<(int)(((long)BB*TA*CC + 255)/256), 256>>>(x, persist, xa);
    // 7) hln = LN1(xa)
    ln_k<<<BB*TA, 256>>>(xa, ln1_w, ln1_b, hln);
    // 8) qkv = hln @ attn_w.T + attn_b
    gemm_k<0,1,ACT_NONE,0><<<gblk(3*CC, TA, BB), thG>>>(hln, attn_w, attn_b, qkv,
        TA, 3*CC, CC, CC, CC, 3*CC, sAC,0, 0,0, sA3C,0, 0, 1, 1.f);
    // 9-11) fused flash attention -> y
    attn_k<<<dim3((TA + 63)/64, HH, BB), thA, ATTN_SMEM>>>(qkv, y);
    // 12) xa += y @ aproj_w.T + aproj_b
    gemm_k<0,1,ACT_NONE,1><<<gblk(CC, TA, BB), thG>>>(y, aproj_w, aproj_b, xa,
        TA, CC, CC, CC, CC, CC, sAC,0, 0,0, sAC,0, 0, 1, 1.f);
    // 13) h2 = LN2(xa)  (reuse hln)
    ln_k<<<BB*TA, 256>>>(xa, ln2_w, ln2_b, hln);
    // 14) fc = gelu(h2 @ fc_w.T + fc_b)
    gemm_k<0,1,ACT_GELU,0><<<gblk(4*CC, TA, BB), thG>>>(hln, fc_w, fc_b, fc,
        TA, 4*CC, CC, CC, CC, 4*CC, sAC,0, 0,0, sA4C,0, 0, 1, 1.f);
    // 15) xa += fc @ mproj_w.T + mproj_b
    gemm_k<0,1,ACT_NONE,1><<<gblk(CC, TA, BB), thG>>>(fc, mproj_w, mproj_b, xa,
        TA, CC, 4*CC, 4*CC, 4*CC, CC, sA4C,0, 0,0, sAC,0, 0, 1, 1.f);
    // 16) out = xa[:, prefix:]
    copy_out_k<<<(int)(((long)BB*TT*CC + 255)/256), 256>>>(xa, out);
    // 17/18) keys -> x2, vals -> x3
    gemm_k<0,1,ACT_NONE,0><<<gblk(CC, TT, BB), thG>>>(xa + PREFIX*CC, k_w, k_b, x2,
        TT, CC, CC, CC, CC, CC, sAC,0, 0,0, sTC,0, 0, 1, 1.f);
    gemm_k<0,1,ACT_NONE,0><<<gblk(CC, TT, BB), thG>>>(xa + PREFIX*CC, v_w, v_b, x3,
        TT, CC, CC, CC, CC, CC, sAC,0, 0,0, sTC,0, 0, 1, 1.f);
    // 19) pre = keys @ w0.T + b0       -> bufA
    gemm_k<0,1,ACT_NONE,0><<<gblk(HID, TT, BB), thG>>>(x2, mem_w0, mem_b0, bufA,
        TT, HID, CC, CC, CC, HID, sTC,0, sWH0,0, sTH,0, HID, 1, 1.f);
    // 20) hh = silu(pre)               -> bufB
    silu_k<<<(int)(((long)BB*TT*HID + 255)/256), 256>>>(bufA, bufB, (long)BB*TT*HID);
    // 21) pred = hh @ w1.T + b1        -> x1
    gemm_k<0,1,ACT_NONE,0><<<gblk(CC, TT, BB), thG>>>(bufB, mem_w1, mem_b1, x1,
        TT, CC, HID, HID, HID, CC, sTH,0, sWH1,0, sTC,0, CC, 1, 1.f);
    // 22) d_pred = 2/(T*C) * (pred - vals), in place in x1
    dpred_k<<<(int)(((long)BB*TT*CC + 255)/256), 256>>>(x1, x3,
        2.f / (float)(TT * CC), (long)BB*TT*CC);
    // 23) g_w1 = d_pred.T @ hh   (TN)
    gemm_k<1,0,ACT_NONE,0><<<gblk(HID, CC, BB), thG>>>(x1, bufB, nullptr, gw1,
        CC, HID, TT, CC, HID, HID, sTC,0, sTH,0, sWH1,0, 0, 1, 1.f);
    // 24) g_b1 = colsum(d_pred)
    colsum_k<<<(BB*CC + 255)/256, 256>>>(x1, gb1, TT, CC);
    // 25) d_hh = d_pred @ w1   (NN)    -> bufC
    gemm_k<0,0,ACT_NONE,0><<<gblk(HID, TT, BB), thG>>>(x1, mem_w1, nullptr, bufC,
        TT, HID, CC, CC, HID, HID, sTC,0, sWH1,0, sTH,0, 0, 1, 1.f);
    // 26) d_pre = d_hh * silu'(pre), in place in bufC
    dpre_k<<<(int)(((long)BB*TT*HID + 255)/256), 256>>>(bufC, bufA, (long)BB*TT*HID);
    // 27) g_w0 = d_pre.T @ keys   (TN)
    gemm_k<1,0,ACT_NONE,0><<<gblk(CC, HID, BB), thG>>>(bufC, x2, nullptr, gw0,
        HID, CC, TT, HID, CC, CC, sTH,0, sTC,0, sWH0,0, 0, 1, 1.f);
    // 28) g_b0 = colsum(d_pre)
    colsum_k<<<(BB*HID + 255)/256, 256>>>(bufC, gb0, TT, HID);

    // 29) momentum + decay updates -> output segments
    const long n_out = (long)BB*TT*CC;
    const long n_w0  = (long)BB*HID*CC;
    const long n_b0  = (long)BB*HID;
    const long n_w1  = (long)BB*CC*HID;
    const long n_b1  = (long)BB*CC;
    float* o_nw0 = out + n_out;
    float* o_nb0 = o_nw0 + n_w0;
    float* o_nw1 = o_nb0 + n_b0;
    float* o_nb1 = o_nw1 + n_w1;
    float* o_mw0 = o_nb1 + n_b1;
    float* o_mb0 = o_mw0 + n_w0;
    float* o_mw1 = o_mb0 + n_b0;
    float* o_mb1 = o_mw1 + n_w1;
    update_k<<<(int)((n_w0 + 255)/256), 256>>>(mem_w0, mom_w0, gw0, o_nw0, o_mw0, n_w0);
    update_k<<<(int)((n_b0 + 255)/256), 256>>>(mem_b0, mom_b0, gb0, o_nb0, o_mb0, n_b0);
    update_k<<<(int)((n_w1 + 255)/256), 256>>>(mem_w1, mom_w1, gw1, o_nw1, o_mw1, n_w1);
    update_k<<<(int)((n_b1 + 255)/256), 256>>>(mem_b1, mom_b1, gb1, o_nb1, o_mb1, n_b1);
}

// round 16
// speedup vs baseline: 2.2171x; 1.8671x over previous
#include <cuda_runtime.h>
#include <cuda_fp16.h>
#include <mma.h>
#include <math.h>

using namespace nvcuda;

// ---------------- problem constants ----------------
static constexpr int BB   = 8;
static constexpr int TT   = 1024;
static constexpr int CC   = 768;
static constexpr int HH   = 12;
static constexpr int HID  = 1536;
static constexpr int MM   = 16;
static constexpr int PP   = 4;
static constexpr int PREFIX = MM + PP;          // 20
static constexpr int TA   = TT + PREFIX;        // 1044
static constexpr int DH   = CC / HH;            // 64
static constexpr float LR = 0.01f, MUc = 0.9f, DECAY = 0.001f;

// ---------------- scratch (device globals; allocation-free) ----------------
__device__ float g_a  [BB*TT*HID];   // mem-fwd hidden | bwd pre
__device__ float g_b  [BB*TT*HID];   // bwd hh
__device__ float g_c  [BB*TT*HID];   // bwd d_hh/d_pre
__device__ float g_x1 [BB*TT*CC];    // q proj | d_pred(unscaled)
__device__ float g_x2 [BB*TT*CC];    // mem out | keys
__device__ float g_x3 [BB*TT*CC];    // vals
__device__ float g_pool[BB*MM*CC];
__device__ float g_xa [BB*TA*CC];
__device__ float g_hln[BB*TA*CC];
__device__ float g_qkv[BB*TA*3*CC];
__device__ float g_y  [BB*TA*CC];
__device__ float g_fc [BB*TA*4*CC];
__device__ float g_gw0[BB*HID*CC];
__device__ float g_gw1[BB*CC*HID];
__device__ float g_gb0[BB*HID];
__device__ float g_gb1[BB*CC];

// ---------------- generic batched GEMM (fp16 WMMA m16n16k16, fp32 accum) ----
// C[z] = beta*C[z] + act(alpha * opA(A[z]) @ opB(B[z]) + bias)
// TRA==1 -> read A[k*lda+m]; TRB==1 -> x @ W^T (read B[n*ldb+k])
// Tile 128x128, k-step 32 (two k16 wmma steps). 256 threads = 8 warps,
// each warp owns 64x32 = 4x2 fragments. float->half conversion at smem fill.
// smem: As[k][m] (col-major for matrix_a), Bs[k][n] (row-major for matrix_b).
enum { ACT_NONE = 0, ACT_SILU = 1, ACT_GELU = 2 };

template<int TRA, int TRB, int ACT, int BETA>
__global__ void __launch_bounds__(256) gemm_k(
    const float* __restrict__ A, const float* __restrict__ Bm,
    const float* __restrict__ bias, float* __restrict__ Cm,
    int M, int N, int K, int lda, int ldb, int ldc,
    long sAb, long sAh, long sBb, long sBh,
    long sCb, long sCh, long sBiasB,
    int inner, float alpha)
{
    const int z  = blockIdx.z;
    const int bo = z / inner, ho = z - bo * inner;
    A  += (long)bo * sAb + (long)ho * sAh;
    Bm += (long)bo * sBb + (long)ho * sBh;
    Cm += (long)bo * sCb + (long)ho * sCh;
    if (bias) bias += (long)bo * sBiasB;

    __shared__ __align__(16) __half As[32][136];   // 272B rows (16B multiple)
    __shared__ __align__(16) __half Bs[32][136];
    __shared__ __align__(16) float  Cs[8][256];    // per-warp 16x16 staging

    const int m0 = blockIdx.y * 128, n0 = blockIdx.x * 128;
    const int tid  = threadIdx.x;
    const int warp = tid >> 5, lane = tid & 31;
    const int wm = (warp >> 2) * 64;    // warp m-offset (0 or 64)
    const int wn = (warp & 3) * 32;     // warp n-offset (0,32,64,96)

    wmma::fragment<wmma::accumulator, 16, 16, 16, float> acc[4][2];
    #pragma unroll
    for (int i = 0; i < 4; i++)
        #pragma unroll
        for (int j = 0; j < 2; j++)
            wmma::fill_fragment(acc[i][j], 0.f);

    for (int k0 = 0; k0 < K; k0 += 32) {
        // ---- fill A tile (128 m x 32 k = 4096 half, 16/thread) ----
        #pragma unroll
        for (int i = 0; i < 16; i++) {
            const int l = tid + i * 256;
            int mm, kk;
            if (TRA == 0) { kk = l & 31; mm = l >> 5; }     // coalesced over gk
            else          { mm = l & 127; kk = l >> 7; }    // coalesced over gm
            const int gm = m0 + mm, gk = k0 + kk;
            float v = 0.f;
            if (gm < M && gk < K)
                v = (TRA == 0) ? A[(long)gm * lda + gk] : A[(long)gk * lda + gm];
            As[kk][mm] = __float2half_rn(v);
        }
        // ---- fill B tile (128 n x 32 k) ----
        #pragma unroll
        for (int i = 0; i < 16; i++) {
            const int l = tid + i * 256;
            int nn, kk;
            if (TRB == 0) { nn = l & 127; kk = l >> 7; }    // coalesced over gn
            else          { kk = l & 31;  nn = l >> 5; }    // coalesced over gk
            const int gn = n0 + nn, gk = k0 + kk;
            float v = 0.f;
            if (gn < N && gk < K)
                v = (TRB == 0) ? Bm[(long)gk * ldb + gn] : Bm[(long)gn * ldb + gk];
            Bs[kk][nn] = __float2half_rn(v);
        }
        __syncthreads();

        #pragma unroll
        for (int ks = 0; ks < 32; ks += 16) {
            wmma::fragment<wmma::matrix_a, 16, 16, 16, __half, wmma::col_major> af[4];
            wmma::fragment<wmma::matrix_b, 16, 16, 16, __half, wmma::row_major> bf[2];
            #pragma unroll
            for (int i = 0; i < 4; i++)
                wmma::load_matrix_sync(af[i], &As[ks][wm + i * 16], 136);
            #pragma unroll
            for (int j = 0; j < 2; j++)
                wmma::load_matrix_sync(bf[j], &Bs[ks][wn + j * 16], 136);
            #pragma unroll
            for (int i = 0; i < 4; i++)
                #pragma unroll
                for (int j = 0; j < 2; j++)
                    wmma::mma_sync(acc[i][j], af[i], bf[j], acc[i][j]);
        }
        __syncthreads();
    }

    // ---- epilogue: stage each 16x16 fragment, apply alpha/bias/act/beta ----
    #pragma unroll
    for (int i = 0; i < 4; i++) {
        #pragma unroll
        for (int j = 0; j < 2; j++) {
            wmma::store_matrix_sync(&Cs[warp][0], acc[i][j], 16, wmma::mem_row_major);
            __syncwarp();
            const int gmb = m0 + wm + i * 16;
            const int gnb = n0 + wn + j * 16;
            #pragma unroll
            for (int e = 0; e < 8; e++) {
                const int idx2 = lane + e * 32;
                const int r = idx2 >> 4, c = idx2 & 15;
                const int gm = gmb + r, gn = gnb + c;
                if (gm < M && gn < N) {
                    float v = alpha * Cs[warp][idx2];
                    if (bias) v += bias[gn];
                    if (ACT == ACT_SILU)      v = v / (1.f + expf(-v));
                    else if (ACT == ACT_GELU) v = 0.5f * v * (1.f + erff(v * 0.70710678118654752f));
                    const long oidx = (long)gm * ldc + gn;
                    if (BETA) Cm[oidx] += v; else Cm[oidx] = v;
                }
            }
            __syncwarp();
        }
    }
}

// ---------------- fused flash attention (prefix-causal, fp32) ----------------
__global__ void attn_k(const float* __restrict__ qkv, float* __restrict__ y)
{
    extern __shared__ float sm[];
    float* Qs = sm;                 // [64][64]
    float* Ks = sm + 64*64;         // [64][65], reused for V
    float* Ps = Ks + 64*65;         // [64][65]

    const int b = blockIdx.z, h = blockIdx.y;
    const int q0 = blockIdx.x * 64;
    const int tx = threadIdx.x, ty = threadIdx.y;
    const int tid = ty * 16 + tx;

    const float* Qp = qkv + (long)b * TA * 3 * CC + h * DH;
    const float* Kp = Qp + CC;
    const float* Vp = Qp + 2 * CC;

    #pragma unroll
    for (int r = 0; r < 16; r++) {
        const int l = tid + r * 256;
        const int i = l >> 6, d = l & 63;
        const int gi = q0 + i;
        Qs[i * 64 + d] = (gi < TA) ? Qp[(long)gi * 3 * CC + d] : 0.f;
    }

    float m_i[4], l_i[4], o[4][4];
    #pragma unroll
    for (int i = 0; i < 4; i++) {
        m_i[i] = -INFINITY; l_i[i] = 0.f;
        #pragma unroll
        for (int j = 0; j < 4; j++) o[i][j] = 0.f;
    }

    const int kmax = (q0 == 0) ? TA : min(TA, q0 + 64);

    for (int k0 = 0; k0 < kmax; k0 += 64) {
        __syncthreads();
        #pragma unroll
        for (int r = 0; r < 16; r++) {
            const int l = tid + r * 256;
            const int j = l >> 6, d = l & 63;
            const int gj = k0 + j;
            Ks[j * 65 + d] = (gj < TA) ? Kp[(long)gj * 3 * CC + d] : 0.f;
        }
        __syncthreads();

        float s[4][4] = {};
        #pragma unroll
        for (int d = 0; d < 64; d++) {
            float a[4], bb[4];
            #pragma unroll
            for (int i = 0; i < 4; i++) a[i]  = Qs[(ty * 4 + i) * 64 + d];
            #pragma unroll
            for (int j = 0; j < 4; j++) bb[j] = Ks[(tx * 4 + j) * 65 + d];
            #pragma unroll
            for (int i = 0; i < 4; i++)
                #pragma unroll
                for (int j = 0; j < 4; j++)
                    s[i][j] += a[i] * bb[j];
        }

        #pragma unroll
        for (int i = 0; i < 4; i++) {
            const int gi = q0 + ty * 4 + i;
            float tm = -INFINITY;
            #pragma unroll
            for (int j = 0; j < 4; j++) {
                const int gj = k0 + tx * 4 + j;
                const bool valid = (gj < TA) && (gi < TA) && (gi < PREFIX || gj <= gi);
                s[i][j] = valid ? s[i][j] * 0.125f : -INFINITY;
                tm = fmaxf(tm, s[i][j]);
            }
            #pragma unroll
            for (int off = 8; off > 0; off >>= 1)
                tm = fmaxf(tm, __shfl_xor_sync(0xffffffffu, tm, off, 16));
            const float newm = fmaxf(m_i[i], tm);
            const float alpha = __expf(m_i[i] - newm);
            float rs = 0.f;
            #pragma unroll
            for (int j = 0; j < 4; j++) {
                const float p = __expf(s[i][j] - newm);
                s[i][j] = p;
                rs += p;
            }
            #pragma unroll
            for (int off = 8; off > 0; off >>= 1)
                rs += __shfl_xor_sync(0xffffffffu, rs, off, 16);
            l_i[i] = l_i[i] * alpha + rs;
            m_i[i] = newm;
            #pragma unroll
            for (int j = 0; j < 4; j++) o[i][j] *= alpha;
            #pragma unroll
            for (int j = 0; j < 4; j++)
                Ps[(ty * 4 + i) * 65 + tx * 4 + j] = s[i][j];
        }
        __syncthreads();

        #pragma unroll
        for (int r = 0; r < 16; r++) {
            const int l = tid + r * 256;
            const int j = l >> 6, d = l & 63;
            const int gj = k0 + j;
            Ks[j * 65 + d] = (gj < TA) ? Vp[(long)gj * 3 * CC + d] : 0.f;
        }
        __syncthreads();

        #pragma unroll
        for (int jj = 0; jj < 64; jj++) {
            float a[4], bb[4];
            #pragma unroll
            for (int i = 0; i < 4; i++) a[i]  = Ps[(ty * 4 + i) * 65 + jj];
            #pragma unroll
            for (int d = 0; d < 4; d++) bb[d] = Ks[jj * 65 + tx * 4 + d];
            #pragma unroll
            for (int i = 0; i < 4; i++)
                #pragma unroll
                for (int d = 0; d < 4; d++)
                    o[i][d] += a[i] * bb[d];
        }
    }

    #pragma unroll
    for (int i = 0; i < 4; i++) {
        const int gi = q0 + ty * 4 + i;
        if (gi >= TA) continue;
        const float inv = 1.f / l_i[i];
        #pragma unroll
        for (int d = 0; d < 4; d++)
            y[(long)b * TA * CC + (long)gi * CC + h * DH + tx * 4 + d] = o[i][d] * inv;
    }
}

// ---------------- layernorm ----------------
__global__ void ln_k(const float* __restrict__ x, const float* __restrict__ w,
                     const float* __restrict__ b, float* __restrict__ out)
{
    const long r = blockIdx.x;
    const float* xr = x + r * CC;
    __shared__ float red[256];
    float s = 0.f;
    for (int c = threadIdx.x; c < CC; c += 256) s += xr[c];
    red[threadIdx.x] = s; __syncthreads();
    for (int o = 128; o > 0; o >>= 1) { if (threadIdx.x < o) red[threadIdx.x] += red[threadIdx.x + o]; __syncthreads(); }
    const float mu = red[0] / CC;
    __syncthreads();
    float v = 0.f;
    for (int c = threadIdx.x; c < CC; c += 256) { const float d = xr[c] - mu; v += d * d; }
    red[threadIdx.x] = v; __syncthreads();
    for (int o = 128; o > 0; o >>= 1) { if (threadIdx.x < o) red[threadIdx.x] += red[threadIdx.x + o]; __syncthreads(); }
    const float inv = rsqrtf(red[0] / CC + 1e-5f);
    for (int c = threadIdx.x; c < CC; c += 256)
        out[r * CC + c] = (xr[c] - mu) * inv * w[c] + b[c];
}

// ---------------- small helpers ----------------
__global__ void pool_k(const float* __restrict__ mem, float* __restrict__ pooled)
{
    const int idx = blockIdx.x * 256 + threadIdx.x;
    if (idx >= BB * MM * CC) return;
    const int c = idx % CC, m = (idx / CC) % MM, b = idx / (CC * MM);
    const float* p = mem + ((long)b * TT + m * (TT / MM)) * CC + c;
    float s = 0.f;
    #pragma unroll 4
    for (int j = 0; j < TT / MM; j++) s += p[(long)j * CC];
    pooled[idx] = s * (1.f / (TT / MM));
}

__global__ void fill_xa_k(const float* __restrict__ x, const float* __restrict__ persist,
                          float* __restrict__ xa)
{
    const long idx = blockIdx.x * 256L + threadIdx.x;
    if (idx >= (long)BB * TA * CC) return;
    const int c = (int)(idx % CC);
    const long rc = idx / CC;
    const int t = (int)(rc % TA);
    const int b = (int)(rc / TA);
    if (t < MM) return;
    if (t < PREFIX) xa[idx] = persist[(t - MM) * CC + c];
    else            xa[idx] = x[((long)b * TT + (t - PREFIX)) * CC + c];
}

__global__ void copy_out_k(const float* __restrict__ xa, float* __restrict__ out)
{
    const long idx = blockIdx.x * 256L + threadIdx.x;
    if (idx >= (long)BB * TT * CC) return;
    const int c = (int)(idx % CC);
    const long rc = idx / CC;
    const int t = (int)(rc % TT);
    const int b = (int)(rc / TT);
    out[idx] = xa[((long)b * TA + PREFIX + t) * CC + c];
}

__global__ void silu_k(const float* __restrict__ pre, float* __restrict__ hh, long n)
{
    const long i = blockIdx.x * 256L + threadIdx.x;
    if (i >= n) return;
    const float z = pre[i];
    hh[i] = z / (1.f + expf(-z));
}

__global__ void dpred_k(float* __restrict__ pred, const float* __restrict__ vals, float coef, long n)
{
    const long i = blockIdx.x * 256L + threadIdx.x;
    if (i >= n) return;
    pred[i] = coef * (pred[i] - vals[i]);
}

__global__ void dpre_k(float* __restrict__ dhh, const float* __restrict__ pre, long n)
{
    const long i = blockIdx.x * 256L + threadIdx.x;
    if (i >= n) return;
    const float z = pre[i];
    const float s = 1.f / (1.f + expf(-z));
    dhh[i] *= s * (1.f + z * (1.f - s));
}

__global__ void colsum_k(const float* __restrict__ a, float* __restrict__ out,
                         int rows, int cols, float coef)
{
    const int idx = blockIdx.x * 256 + threadIdx.x;
    if (idx >= BB * cols) return;
    const int c = idx % cols, b = idx / cols;
    const float* p = a + (long)b * rows * cols + c;
    float s = 0.f;
    for (int t = 0; t < rows; t++) s += p[(long)t * cols];
    out[idx] = s * coef;
}

__global__ void update_k(const float* __restrict__ w, const float* __restrict__ mom,
                         const float* __restrict__ g,
                         float* __restrict__ nw, float* __restrict__ nmom, long n)
{
    const long i = blockIdx.x * 256L + threadIdx.x;
    if (i >= n) return;
    const float nm = MUc * mom[i] + g[i];
    nmom[i] = nm;
    nw[i] = (1.f - DECAY) * w[i] - LR * nm;
}

// ---------------- host orchestration ----------------
static inline dim3 gblk(int N, int M, int Z) { return dim3((N + 127) / 128, (M + 127) / 128, Z); }

extern "C" void kernel_launch(void* const* d_in, const int* in_sizes, int n_in,
                              void* d_out, int out_size)
{
    const float* x        = (const float*)d_in[0];
    const float* persist  = (const float*)d_in[1];
    const float* ln1_w    = (const float*)d_in[2];
    const float* ln1_b    = (const float*)d_in[3];
    const float* ln2_w    = (const float*)d_in[4];
    const float* ln2_b    = (const float*)d_in[5];
    const float* attn_w   = (const float*)d_in[6];
    const float* attn_b   = (const float*)d_in[7];
    const float* aproj_w  = (const float*)d_in[8];
    const float* aproj_b  = (const float*)d_in[9];
    const float* fc_w     = (const float*)d_in[10];
    const float* fc_b     = (const float*)d_in[11];
    const float* mproj_w  = (const float*)d_in[12];
    const float* mproj_b  = (const float*)d_in[13];
    const float* q_w      = (const float*)d_in[14];
    const float* q_b      = (const float*)d_in[15];
    const float* k_w      = (const float*)d_in[16];
    const float* k_b      = (const float*)d_in[17];
    const float* v_w      = (const float*)d_in[18];
    const float* v_b      = (const float*)d_in[19];
    const float* o_w      = (const float*)d_in[20];
    const float* o_b      = (const float*)d_in[21];
    const float* mem_w0   = (const float*)d_in[22];
    const float* mem_b0   = (const float*)d_in[23];
    const float* mem_w1   = (const float*)d_in[24];
    const float* mem_b1   = (const float*)d_in[25];
    const float* mom_w0   = (const float*)d_in[26];
    const float* mom_b0   = (const float*)d_in[27];
    const float* mom_w1   = (const float*)d_in[28];
    const float* mom_b1   = (const float*)d_in[29];
    float* out = (float*)d_out;

    float *bufA, *bufB, *bufC, *x1, *x2, *x3, *pool, *xa, *hln, *qkv, *fc, *y,
          *gw0, *gw1, *gb0, *gb1;
    cudaGetSymbolAddress((void**)&bufA, g_a);
    cudaGetSymbolAddress((void**)&bufB, g_b);
    cudaGetSymbolAddress((void**)&bufC, g_c);
    cudaGetSymbolAddress((void**)&x1,   g_x1);
    cudaGetSymbolAddress((void**)&x2,   g_x2);
    cudaGetSymbolAddress((void**)&x3,   g_x3);
    cudaGetSymbolAddress((void**)&pool, g_pool);
    cudaGetSymbolAddress((void**)&xa,   g_xa);
    cudaGetSymbolAddress((void**)&hln,  g_hln);
    cudaGetSymbolAddress((void**)&qkv,  g_qkv);
    cudaGetSymbolAddress((void**)&fc,   g_fc);
    cudaGetSymbolAddress((void**)&y,    g_y);
    cudaGetSymbolAddress((void**)&gw0,  g_gw0);
    cudaGetSymbolAddress((void**)&gw1,  g_gw1);
    cudaGetSymbolAddress((void**)&gb0,  g_gb0);
    cudaGetSymbolAddress((void**)&gb1,  g_gb1);

    const int ATTN_SMEM = (64*64 + 2*64*65) * (int)sizeof(float);   // 49,664 B
    cudaFuncSetAttribute(attn_k, cudaFuncAttributeMaxDynamicSharedMemorySize, ATTN_SMEM);

    const dim3 thG(256);
    const dim3 thA(16, 16);
    const long sTC  = (long)TT * CC;
    const long sTH  = (long)TT * HID;
    const long sAC  = (long)TA * CC;
    const long sA3C = (long)TA * 3 * CC;
    const long sA4C = (long)TA * 4 * CC;
    const long sWH0 = (long)HID * CC;
    const long sWH1 = (long)CC * HID;
    const float coef = 2.f / (float)(TT * CC);

    // 1) q = x @ q_w.T + q_b           -> x1
    gemm_k<0,1,ACT_NONE,0><<<gblk(CC, TT, BB), thG>>>(x, q_w, q_b, x1,
        TT, CC, CC, CC, CC, CC, sTC,0, 0,0, sTC,0, 0, 1, 1.f);
    // 2) h = silu(q @ w0_b.T + b0_b)   -> bufA
    gemm_k<0,1,ACT_SILU,0><<<gblk(HID, TT, BB), thG>>>(x1, mem_w0, mem_b0, bufA,
        TT, HID, CC, CC, CC, HID, sTC,0, sWH0,0, sTH,0, HID, 1, 1.f);
    // 3) mem = h @ w1_b.T + b1_b       -> x2
    gemm_k<0,1,ACT_NONE,0><<<gblk(CC, TT, BB), thG>>>(bufA, mem_w1, mem_b1, x2,
        TT, CC, HID, HID, HID, CC, sTH,0, sWH1,0, sTC,0, CC, 1, 1.f);
    // 4) pooled = segment mean
    pool_k<<<(BB*MM*CC + 255)/256, 256>>>(x2, pool);
    // 5) retrieved -> xa rows [0,16)
    gemm_k<0,1,ACT_NONE,0><<<gblk(CC, MM, BB), thG>>>(pool, o_w, o_b, xa,
        MM, CC, CC, CC, CC, CC, (long)MM*CC,0, 0,0, sAC,0, 0, 1, 1.f);
    // 6) persist + x -> xa rows [16,ta)
    fill_xa_k<<<(int)(((long)BB*TA*CC + 255)/256), 256>>>(x, persist, xa);
    // 7) hln = LN1(xa)
    ln_k<<<BB*TA, 256>>>(xa, ln1_w, ln1_b, hln);
    // 8) qkv = hln @ attn_w.T + attn_b
    gemm_k<0,1,ACT_NONE,0><<<gblk(3*CC, TA, BB), thG>>>(hln, attn_w, attn_b, qkv,
        TA, 3*CC, CC, CC, CC, 3*CC, sAC,0, 0,0, sA3C,0, 0, 1, 1.f);
    // 9-11) fused flash attention -> y
    attn_k<<<dim3((TA + 63)/64, HH, BB), thA, ATTN_SMEM>>>(qkv, y);
    // 12) xa += y @ aproj_w.T + aproj_b
    gemm_k<0,1,ACT_NONE,1><<<gblk(CC, TA, BB), thG>>>(y, aproj_w, aproj_b, xa,
        TA, CC, CC, CC, CC, CC, sAC,0, 0,0, sAC,0, 0, 1, 1.f);
    // 13) h2 = LN2(xa)  (reuse hln)
    ln_k<<<BB*TA, 256>>>(xa, ln2_w, ln2_b, hln);
    // 14) fc = gelu(h2 @ fc_w.T + fc_b)
    gemm_k<0,1,ACT_GELU,0><<<gblk(4*CC, TA, BB), thG>>>(hln, fc_w, fc_b, fc,
        TA, 4*CC, CC, CC, CC, 4*CC, sAC,0, 0,0, sA4C,0, 0, 1, 1.f);
    // 15) xa += fc @ mproj_w.T + mproj_b
    gemm_k<0,1,ACT_NONE,1><<<gblk(CC, TA, BB), thG>>>(fc, mproj_w, mproj_b, xa,
        TA, CC, 4*CC, 4*CC, 4*CC, CC, sA4C,0, 0,0, sAC,0, 0, 1, 1.f);
    // 16) out = xa[:, prefix:]
    copy_out_k<<<(int)(((long)BB*TT*CC + 255)/256), 256>>>(xa, out);
    // 17/18) keys -> x2, vals -> x3
    gemm_k<0,1,ACT_NONE,0><<<gblk(CC, TT, BB), thG>>>(xa + PREFIX*CC, k_w, k_b, x2,
        TT, CC, CC, CC, CC, CC, sAC,0, 0,0, sTC,0, 0, 1, 1.f);
    gemm_k<0,1,ACT_NONE,0><<<gblk(CC, TT, BB), thG>>>(xa + PREFIX*CC, v_w, v_b, x3,
        TT, CC, CC, CC, CC, CC, sAC,0, 0,0, sTC,0, 0, 1, 1.f);
    // 19) pre = keys @ w0.T + b0       -> bufA
    gemm_k<0,1,ACT_NONE,0><<<gblk(HID, TT, BB), thG>>>(x2, mem_w0, mem_b0, bufA,
        TT, HID, CC, CC, CC, HID, sTC,0, sWH0,0, sTH,0, HID, 1, 1.f);
    // 20) hh = silu(pre)               -> bufB
    silu_k<<<(int)(((long)BB*TT*HID + 255)/256), 256>>>(bufA, bufB, (long)BB*TT*HID);
    // 21) pred = hh @ w1.T + b1        -> x1
    gemm_k<0,1,ACT_NONE,0><<<gblk(CC, TT, BB), thG>>>(bufB, mem_w1, mem_b1, x1,
        TT, CC, HID, HID, HID, CC, sTH,0, sWH1,0, sTC,0, CC, 1, 1.f);
    // 22) d_pred = (pred - vals) UNSCALED (coef applied in grad GEMMs/colsums
    //     to avoid fp16 underflow of ~1e-7 values)
    dpred_k<<<(int)(((long)BB*TT*CC + 255)/256), 256>>>(x1, x3, 1.f, (long)BB*TT*CC);
    // 23) g_w1 = coef * d_pred.T @ hh   (TN)
    gemm_k<1,0,ACT_NONE,0><<<gblk(HID, CC, BB), thG>>>(x1, bufB, nullptr, gw1,
        CC, HID, TT, CC, HID, HID, sTC,0, sTH,0, sWH1,0, 0, 1, coef);
    // 24) g_b1 = coef * colsum(d_pred)
    colsum_k<<<(BB*CC + 255)/256, 256>>>(x1, gb1, TT, CC, coef);
    // 25) d_hh = d_pred @ w1   (NN, unscaled) -> bufC
    gemm_k<0,0,ACT_NONE,0><<<gblk(HID, TT, BB), thG>>>(x1, mem_w1, nullptr, bufC,
        TT, HID, CC, CC, HID, HID, sTC,0, sWH1,0, sTH,0, 0, 1, 1.f);
    // 26) d_pre = d_hh * silu'(pre), in place (unscaled)
    dpre_k<<<(int)(((long)BB*TT*HID + 255)/256), 256>>>(bufC, bufA, (long)BB*TT*HID);
    // 27) g_w0 = coef * d_pre.T @ keys   (TN)
    gemm_k<1,0,ACT_NONE,0><<<gblk(CC, HID, BB), thG>>>(bufC, x2, nullptr, gw0,
        HID, CC, TT, HID, CC, CC, sTH,0, sTC,0, sWH0,0, 0, 1, coef);
    // 28) g_b0 = coef * colsum(d_pre)
    colsum_k<<<(BB*HID + 255)/256, 256>>>(bufC, gb0, TT, HID, coef);

    // 29) momentum + decay updates -> output segments
    const long n_out = (long)BB*TT*CC;
    const long n_w0  = (long)BB*HID*CC;
    const long n_b0  = (long)BB*HID;
    const long n_w1  = (long)BB*CC*HID;
    const long n_b1  = (long)BB*CC;
    float* o_nw0 = out + n_out;
    float* o_nb0 = o_nw0 + n_w0;
    float* o_nw1 = o_nb0 + n_b0;
    float* o_nb1 = o_nw1 + n_w1;
    float* o_mw0 = o_nb1 + n_b1;
    float* o_mb0 = o_mw0 + n_w0;
    float* o_mw1 = o_mb0 + n_b0;
    float* o_mb1 = o_mw1 + n_w1;
    update_k<<<(int)((n_w0 + 255)/256), 256>>>(mem_w0, mom_w0, gw0, o_nw0, o_mw0, n_w0);
    update_k<<<(int)((n_b0 + 255)/256), 256>>>(mem_b0, mom_b0, gb0, o_nb0, o_mb0, n_b0);
    update_k<<<(int)((n_w1 + 255)/256), 256>>>(mem_w1, mom_w1, gw1, o_nw1, o_mw1, n_w1);
    update_k<<<(int)((n_b1 + 255)/256), 256>>>(mem_b1, mom_b1, gb1, o_nb1, o_mb1, n_b1);
}